// round 6
// baseline (speedup 1.0000x reference)
#include <cuda_runtime.h>
#include <cuda.h>
#include <cstdint>

// ===========================================================================
// Dense GEMM: out[M,N] = x[M,K] @ weight[N,K]^T + bias[N],  M=N=K=4096, fp32.
//
// Harness PTX target is compute_103 (no 'a') -> tcgen05 is unavailable.
// Engine: warp-level mma.sync m16n8k8 tf32 (sm_80 baseline, compiles clean).
// Data movement: TMA (cp.async.bulk.tensor, sm_90 baseline) + mbarrier
// 4-stage pipeline, SW128 swizzle.
//
// CTA tile 128x128, K-chunk 32 f32 (128B rows). 9 warps: 8 compute (4M x 2N,
// warp tile 32x64), 1 TMA producer. Accumulators in registers.
// ===========================================================================

#define M_TILE   128
#define N_TILE   128
#define K_TILE   32
#define NUM_IT   128           // 4096 / 32
#define STAGES   4

static constexpr int A_BYTES     = M_TILE * 128;             // 16384
static constexpr int B_BYTES     = N_TILE * 128;             // 16384
static constexpr int STAGE_BYTES = A_BYTES + B_BYTES;        // 32768
static constexpr int SM_BAR      = 0;                        // barrier block
static constexpr int SM_TILES    = 1024;                     // 1024-aligned tiles
static constexpr int SMEM_TOTAL  = SM_TILES + STAGES * STAGE_BYTES;  // 132096

// ---------------------------------------------------------------------------
// PTX helpers (sm_90-baseline features only — NO 'a'-suffix instructions)
// ---------------------------------------------------------------------------
static __device__ __forceinline__ uint32_t smem_u32(const void* p) {
    uint32_t a;
    asm("{ .reg .u64 t; cvta.to.shared.u64 t, %1; cvt.u32.u64 %0, t; }"
        : "=r"(a) : "l"(p));
    return a;
}

static __device__ __forceinline__ uint32_t elect_one() {
    uint32_t pred;
    asm volatile(
        "{\n\t.reg .pred p;\n\t"
        "elect.sync _|p, 0xFFFFFFFF;\n\t"
        "selp.b32 %0, 1, 0, p;\n\t}"
        : "=r"(pred));
    return pred;
}

static __device__ __forceinline__ void mbar_init(uint32_t a, uint32_t cnt) {
    asm volatile("mbarrier.init.shared.b64 [%0], %1;" :: "r"(a), "r"(cnt) : "memory");
}
static __device__ __forceinline__ void mbar_expect_tx(uint32_t a, uint32_t tx) {
    asm volatile("mbarrier.arrive.expect_tx.shared.b64 _, [%0], %1;"
                 :: "r"(a), "r"(tx) : "memory");
}
static __device__ __forceinline__ void mbar_arrive(uint32_t a) {
    asm volatile("mbarrier.arrive.release.cta.shared::cta.b64 _, [%0];"
                 :: "r"(a) : "memory");
}
// Acquire wait: consumers (post-wait generic LDS of the tile data).
static __device__ __forceinline__ void mbar_wait(uint32_t a, uint32_t parity) {
    asm volatile(
        "{\n\t.reg .pred P;\n\t"
        "LWAIT_%=:\n\t"
        "mbarrier.try_wait.parity.acquire.cta.shared::cta.b64 P, [%0], %1, 0x989680;\n\t"
        "@P bra.uni LDONE_%=;\n\t"
        "bra.uni LWAIT_%=;\n\t"
        "LDONE_%=:\n\t}"
        :: "r"(a), "r"(parity) : "memory");
}
// Relaxed wait: producer only (post-wait accesses are all async-proxy TMA).
static __device__ __forceinline__ void mbar_wait_relaxed(uint32_t a, uint32_t parity) {
    asm volatile(
        "{\n\t.reg .pred P;\n\t"
        "RWAIT_%=:\n\t"
        "mbarrier.try_wait.parity.relaxed.cta.shared::cta.b64 P, [%0], %1, 0x989680;\n\t"
        "@P bra.uni RDONE_%=;\n\t"
        "bra.uni RWAIT_%=;\n\t"
        "RDONE_%=:\n\t}"
        :: "r"(a), "r"(parity) : "memory");
}

static __device__ __forceinline__ void tma_load_2d(uint32_t smem_addr, const void* tmap,
                                                   int32_t cx, int32_t cy, uint32_t mbar) {
    asm volatile(
        "cp.async.bulk.tensor.2d.shared::cta.global.tile.mbarrier::complete_tx::bytes "
        "[%0], [%1, {%2, %3}], [%4];"
        :: "r"(smem_addr), "l"(tmap), "r"(cx), "r"(cy), "r"(mbar) : "memory");
}

// m16n8k8 tf32: D(f32 x4) = A(tf32 x4) * B(tf32 x2) + C
static __device__ __forceinline__ void mma_tf32(float* c, const uint32_t* a,
                                                const uint32_t* b) {
    asm volatile(
        "mma.sync.aligned.m16n8k8.row.col.f32.tf32.tf32.f32 "
        "{%0,%1,%2,%3}, {%4,%5,%6,%7}, {%8,%9}, {%0,%1,%2,%3};"
        : "+f"(c[0]), "+f"(c[1]), "+f"(c[2]), "+f"(c[3])
        : "r"(a[0]), "r"(a[1]), "r"(a[2]), "r"(a[3]), "r"(b[0]), "r"(b[1]));
}

// ---------------------------------------------------------------------------
// Kernel
// ---------------------------------------------------------------------------
__global__ void __launch_bounds__(288, 1)
gemm_tf32_kernel(const __grid_constant__ CUtensorMap tmA,
                 const __grid_constant__ CUtensorMap tmB,
                 const float* __restrict__ bias,
                 float* __restrict__ out) {
    extern __shared__ __align__(1024) char smem[];
    const uint32_t sb = smem_u32(smem);
    const int tid = threadIdx.x;
    const int wid = tid >> 5;
    const int lid = tid & 31;

    const int m_base = blockIdx.y * M_TILE;
    const int n_base = blockIdx.x * N_TILE;

    // per-stage barriers at sb + SM_BAR + s*16 (full) / +8 (empty)
    if (tid == 0) {
        #pragma unroll
        for (int s = 0; s < STAGES; s++) {
            mbar_init(sb + SM_BAR + s * 16, 1);       // full: producer expect_tx
            mbar_init(sb + SM_BAR + s * 16 + 8, 8);   // empty: 8 compute warps
        }
    }
    __syncthreads();

    if (wid == 8) {
        // ---------------- TMA producer warp ----------------
        const uint32_t el = elect_one();
        int s = 0;
        uint32_t ep = 0;
        for (int it = 0; it < NUM_IT; ++it) {
            if (it >= STAGES) mbar_wait_relaxed(sb + SM_BAR + s * 16 + 8, ep);
            if (el) {
                const uint32_t stage = sb + SM_TILES + s * STAGE_BYTES;
                mbar_expect_tx(sb + SM_BAR + s * 16, STAGE_BYTES);
                tma_load_2d(stage,           &tmA, it * K_TILE, m_base,
                            sb + SM_BAR + s * 16);
                tma_load_2d(stage + A_BYTES, &tmB, it * K_TILE, n_base,
                            sb + SM_BAR + s * 16);
            }
            if (++s == STAGES) { s = 0; if (it >= STAGES) ep ^= 1; }
        }
        return;
    }

    // ---------------- Compute warps (0-7): 4M x 2N grid, warp tile 32x64 ----
    const int warpM = wid & 3;      // 0..3  -> M offset warpM*32
    const int warpN = wid >> 2;     // 0..1  -> N offset warpN*64
    const int gid   = lid >> 2;     // 0..7
    const int tid4  = lid & 3;      // 0..3

    float acc[2][8][4];             // [mt][nt][frag]
    #pragma unroll
    for (int mt = 0; mt < 2; ++mt)
        #pragma unroll
        for (int nt = 0; nt < 8; ++nt)
            #pragma unroll
            for (int q = 0; q < 4; ++q) acc[mt][nt][q] = 0.0f;

    // SW128 address: addr(r, c) = base + r*128 + tid4*4 + ((q ^ gid) << 4)
    // where c = tid4 + 4*q, and (r & 7) == gid for every row this thread reads.
    const int aRow0 = warpM * 32 + gid;           // mt*16 added in loop; +8 for h=1
    const int bRow0 = warpN * 64 + gid;           // nt*8 added in loop

    int s = 0;
    uint32_t fp = 0;
    for (int it = 0; it < NUM_IT; ++it) {
        mbar_wait(sb + SM_BAR + s * 16, fp);
        const char* sA = smem + SM_TILES + s * STAGE_BYTES;
        const char* sB = sA + A_BYTES;

        #pragma unroll
        for (int ks = 0; ks < 4; ++ks) {
            const int q0 = (2 * ks)     ^ gid;    // 16B-unit index, swizzled
            const int q1 = (2 * ks + 1) ^ gid;
            const int co = tid4 * 4;

            uint32_t a[2][4];
            #pragma unroll
            for (int mt = 0; mt < 2; ++mt) {
                const int r0 = aRow0 + mt * 16;
                const int r1 = r0 + 8;
                a[mt][0] = *(const uint32_t*)(sA + r0 * 128 + co + (q0 << 4));
                a[mt][1] = *(const uint32_t*)(sA + r1 * 128 + co + (q0 << 4));
                a[mt][2] = *(const uint32_t*)(sA + r0 * 128 + co + (q1 << 4));
                a[mt][3] = *(const uint32_t*)(sA + r1 * 128 + co + (q1 << 4));
            }
            uint32_t b[8][2];
            #pragma unroll
            for (int nt = 0; nt < 8; ++nt) {
                const int rb = bRow0 + nt * 8;
                b[nt][0] = *(const uint32_t*)(sB + rb * 128 + co + (q0 << 4));
                b[nt][1] = *(const uint32_t*)(sB + rb * 128 + co + (q1 << 4));
            }
            #pragma unroll
            for (int nt = 0; nt < 8; ++nt)
                #pragma unroll
                for (int mt = 0; mt < 2; ++mt)
                    mma_tf32(acc[mt][nt], a[mt], b[nt]);
        }

        // All warp lanes' LDS are consumed once the mma.sync ops above issued;
        // signal the stage free for the producer.
        if (lid == 0) mbar_arrive(sb + SM_BAR + s * 16 + 8);
        if (++s == STAGES) { s = 0; fp ^= 1; }
    }

    // ---------------- Epilogue: registers -> GMEM (+bias) ----------------
    #pragma unroll
    for (int mt = 0; mt < 2; ++mt) {
        #pragma unroll
        for (int h = 0; h < 2; ++h) {
            const int row = m_base + warpM * 32 + mt * 16 + gid + h * 8;
            float* __restrict__ orow = out + (size_t)row * 4096;
            #pragma unroll
            for (int nt = 0; nt < 8; ++nt) {
                const int col = n_base + warpN * 64 + nt * 8 + tid4 * 2;
                const float2 bv = __ldg((const float2*)(bias + col));
                float2 v;
                v.x = acc[mt][nt][h * 2 + 0] + bv.x;
                v.y = acc[mt][nt][h * 2 + 1] + bv.y;
                *(float2*)(orow + col) = v;
            }
        }
    }
}

// ---------------------------------------------------------------------------
// Host launch (graph-capturable: host-side setup + one kernel launch)
// ---------------------------------------------------------------------------
typedef CUresult (*EncodeTiledFn)(
    CUtensorMap*, CUtensorMapDataType, cuuint32_t, void*,
    const cuuint64_t*, const cuuint64_t*, const cuuint32_t*, const cuuint32_t*,
    CUtensorMapInterleave, CUtensorMapSwizzle, CUtensorMapL2promotion,
    CUtensorMapFloatOOBfill);

extern "C" void kernel_launch(void* const* d_in, const int* in_sizes, int n_in,
                              void* d_out, int out_size) {
    const float* x    = (const float*)d_in[0];   // [4096, 4096]
    const float* w    = (const float*)d_in[1];   // [4096, 4096]
    const float* bias = (const float*)d_in[2];   // [4096]
    float* out        = (float*)d_out;

    void* fn = nullptr;
    cudaDriverEntryPointQueryResult qr;
    cudaGetDriverEntryPoint("cuTensorMapEncodeTiled", &fn, cudaEnableDefault, &qr);
    EncodeTiledFn encode = (EncodeTiledFn)fn;

    alignas(64) CUtensorMap tA, tB;
    cuuint64_t dims[2]    = {4096, 4096};          // {K elems, rows}
    cuuint64_t strides[1] = {4096 * sizeof(float)};
    cuuint32_t box[2]     = {K_TILE, 128};         // 128B x 128 rows
    cuuint32_t es[2]      = {1, 1};

    encode(&tA, CU_TENSOR_MAP_DATA_TYPE_FLOAT32, 2, (void*)x,
           dims, strides, box, es,
           CU_TENSOR_MAP_INTERLEAVE_NONE, CU_TENSOR_MAP_SWIZZLE_128B,
           CU_TENSOR_MAP_L2_PROMOTION_L2_256B, CU_TENSOR_MAP_FLOAT_OOB_FILL_NONE);
    encode(&tB, CU_TENSOR_MAP_DATA_TYPE_FLOAT32, 2, (void*)w,
           dims, strides, box, es,
           CU_TENSOR_MAP_INTERLEAVE_NONE, CU_TENSOR_MAP_SWIZZLE_128B,
           CU_TENSOR_MAP_L2_PROMOTION_L2_256B, CU_TENSOR_MAP_FLOAT_OOB_FILL_NONE);

    cudaFuncSetAttribute(gemm_tf32_kernel,
                         cudaFuncAttributeMaxDynamicSharedMemorySize, SMEM_TOTAL);

    dim3 grid(4096 / N_TILE, 4096 / M_TILE, 1);   // (32, 32)
    gemm_tf32_kernel<<<grid, 288, SMEM_TOTAL>>>(tA, tB, bias, out);
}

// round 7
// speedup vs baseline: 1.0234x; 1.0234x over previous
#include <cuda_runtime.h>
#include <cuda.h>
#include <cstdint>

// ===========================================================================
// Dense GEMM: out[M,N] = x[M,K] @ weight[N,K]^T + bias[N],  M=N=K=4096, fp32.
//
// Harness PTX target is compute_103 (no 'a') -> tcgen05 unavailable.
// Engine: warp-level mma.sync m16n8k8 tf32. Data movement: TMA + mbarrier.
//
// CTA tile 128x128, stage = K64 (two 32-f32 SW128 slabs per operand),
// 3-stage pipeline (64 KB/stage). 9 warps: 8 compute (4M x 2N, warp tile
// 32x64) + 1 TMA producer. Accumulators in registers.
// ===========================================================================

#define M_TILE   128
#define N_TILE   128
#define K_SLAB   32            // f32 per slab (= 128 B SW128 row)
#define K_STAGE  64            // f32 per pipeline stage (2 slabs)
#define NUM_IT   64            // 4096 / 64
#define STAGES   3

static constexpr int SLAB_BYTES  = 128 * 128;                // 16384 (128 rows x 128B)
static constexpr int A_BYTES     = 2 * SLAB_BYTES;           // 32768
static constexpr int B_BYTES     = 2 * SLAB_BYTES;           // 32768
static constexpr int STAGE_BYTES = A_BYTES + B_BYTES;        // 65536
static constexpr int SM_BAR      = 0;
static constexpr int SM_TILES    = 1024;
static constexpr int SMEM_TOTAL  = SM_TILES + STAGES * STAGE_BYTES;  // 197632

// ---------------------------------------------------------------------------
// PTX helpers (sm_90-baseline features only — NO 'a'-suffix instructions)
// ---------------------------------------------------------------------------
static __device__ __forceinline__ uint32_t smem_u32(const void* p) {
    uint32_t a;
    asm("{ .reg .u64 t; cvta.to.shared.u64 t, %1; cvt.u32.u64 %0, t; }"
        : "=r"(a) : "l"(p));
    return a;
}

static __device__ __forceinline__ uint32_t elect_one() {
    uint32_t pred;
    asm volatile(
        "{\n\t.reg .pred p;\n\t"
        "elect.sync _|p, 0xFFFFFFFF;\n\t"
        "selp.b32 %0, 1, 0, p;\n\t}"
        : "=r"(pred));
    return pred;
}

static __device__ __forceinline__ void mbar_init(uint32_t a, uint32_t cnt) {
    asm volatile("mbarrier.init.shared.b64 [%0], %1;" :: "r"(a), "r"(cnt) : "memory");
}
static __device__ __forceinline__ void mbar_expect_tx(uint32_t a, uint32_t tx) {
    asm volatile("mbarrier.arrive.expect_tx.shared.b64 _, [%0], %1;"
                 :: "r"(a), "r"(tx) : "memory");
}
static __device__ __forceinline__ void mbar_arrive(uint32_t a) {
    asm volatile("mbarrier.arrive.release.cta.shared::cta.b64 _, [%0];"
                 :: "r"(a) : "memory");
}
// Acquire wait: consumers (post-wait generic LDS of tile data).
static __device__ __forceinline__ void mbar_wait(uint32_t a, uint32_t parity) {
    asm volatile(
        "{\n\t.reg .pred P;\n\t"
        "LWAIT_%=:\n\t"
        "mbarrier.try_wait.parity.acquire.cta.shared::cta.b64 P, [%0], %1, 0x989680;\n\t"
        "@P bra.uni LDONE_%=;\n\t"
        "bra.uni LWAIT_%=;\n\t"
        "LDONE_%=:\n\t}"
        :: "r"(a), "r"(parity) : "memory");
}
// Relaxed wait: producer only (post-wait accesses are all async-proxy TMA).
static __device__ __forceinline__ void mbar_wait_relaxed(uint32_t a, uint32_t parity) {
    asm volatile(
        "{\n\t.reg .pred P;\n\t"
        "RWAIT_%=:\n\t"
        "mbarrier.try_wait.parity.relaxed.cta.shared::cta.b64 P, [%0], %1, 0x989680;\n\t"
        "@P bra.uni RDONE_%=;\n\t"
        "bra.uni RWAIT_%=;\n\t"
        "RDONE_%=:\n\t}"
        :: "r"(a), "r"(parity) : "memory");
}

static __device__ __forceinline__ void tma_load_2d(uint32_t smem_addr, const void* tmap,
                                                   int32_t cx, int32_t cy, uint32_t mbar) {
    asm volatile(
        "cp.async.bulk.tensor.2d.shared::cta.global.tile.mbarrier::complete_tx::bytes "
        "[%0], [%1, {%2, %3}], [%4];"
        :: "r"(smem_addr), "l"(tmap), "r"(cx), "r"(cy), "r"(mbar) : "memory");
}

// m16n8k8 tf32: D(f32 x4) = A(tf32 x4) * B(tf32 x2) + C
static __device__ __forceinline__ void mma_tf32(float* c, const uint32_t* a,
                                                const uint32_t* b) {
    asm volatile(
        "mma.sync.aligned.m16n8k8.row.col.f32.tf32.tf32.f32 "
        "{%0,%1,%2,%3}, {%4,%5,%6,%7}, {%8,%9}, {%0,%1,%2,%3};"
        : "+f"(c[0]), "+f"(c[1]), "+f"(c[2]), "+f"(c[3])
        : "r"(a[0]), "r"(a[1]), "r"(a[2]), "r"(a[3]), "r"(b[0]), "r"(b[1]));
}

// ---------------------------------------------------------------------------
// Kernel
// ---------------------------------------------------------------------------
__global__ void __launch_bounds__(288, 1)
gemm_tf32_kernel(const __grid_constant__ CUtensorMap tmA,
                 const __grid_constant__ CUtensorMap tmB,
                 const float* __restrict__ bias,
                 float* __restrict__ out) {
    extern __shared__ __align__(1024) char smem[];
    const uint32_t sb = smem_u32(smem);
    const int tid = threadIdx.x;
    const int wid = tid >> 5;
    const int lid = tid & 31;

    const int m_base = blockIdx.y * M_TILE;
    const int n_base = blockIdx.x * N_TILE;

    // per-stage barriers at sb + SM_BAR + s*16 (full) / +8 (empty)
    if (tid == 0) {
        #pragma unroll
        for (int s = 0; s < STAGES; s++) {
            mbar_init(sb + SM_BAR + s * 16, 1);       // full: producer expect_tx
            mbar_init(sb + SM_BAR + s * 16 + 8, 8);   // empty: 8 compute warps
        }
    }
    __syncthreads();

    if (wid == 8) {
        // ---------------- TMA producer warp ----------------
        const uint32_t el = elect_one();
        int s = 0;
        uint32_t ep = 0;
        for (int it = 0; it < NUM_IT; ++it) {
            if (it >= STAGES) mbar_wait_relaxed(sb + SM_BAR + s * 16 + 8, ep);
            if (el) {
                const uint32_t stage = sb + SM_TILES + s * STAGE_BYTES;
                const uint32_t fullb = sb + SM_BAR + s * 16;
                const int kx = it * K_STAGE;
                mbar_expect_tx(fullb, STAGE_BYTES);
                tma_load_2d(stage,                  &tmA, kx,          m_base, fullb);
                tma_load_2d(stage + SLAB_BYTES,     &tmA, kx + K_SLAB, m_base, fullb);
                tma_load_2d(stage + A_BYTES,        &tmB, kx,          n_base, fullb);
                tma_load_2d(stage + A_BYTES + SLAB_BYTES,
                                                    &tmB, kx + K_SLAB, n_base, fullb);
            }
            if (++s == STAGES) { s = 0; if (it >= STAGES) ep ^= 1; }
        }
        return;
    }

    // ---------------- Compute warps (0-7): 4M x 2N grid, warp tile 32x64 ----
    const int warpM = wid & 3;      // M offset warpM*32
    const int warpN = wid >> 2;     // N offset warpN*64
    const int gid   = lid >> 2;     // 0..7
    const int tid4  = lid & 3;      // 0..3

    float acc[2][8][4];
    #pragma unroll
    for (int mt = 0; mt < 2; ++mt)
        #pragma unroll
        for (int nt = 0; nt < 8; ++nt)
            #pragma unroll
            for (int q = 0; q < 4; ++q) acc[mt][nt][q] = 0.0f;

    // SW128: element (r, 16B-unit q) lives at r*128 + ((q ^ (r&7)) << 4).
    // Every row this thread touches has (r & 7) == gid.
    const int aRow0 = warpM * 32 + gid;
    const int bRow0 = warpN * 64 + gid;
    const int co    = tid4 * 4;

    int s = 0;
    uint32_t fp = 0;
    for (int it = 0; it < NUM_IT; ++it) {
        mbar_wait(sb + SM_BAR + s * 16, fp);
        const char* base = smem + SM_TILES + s * STAGE_BYTES;

        #pragma unroll
        for (int slab = 0; slab < 2; ++slab) {
            const char* sA = base + slab * SLAB_BYTES;
            const char* sB = base + A_BYTES + slab * SLAB_BYTES;

            #pragma unroll
            for (int kk = 0; kk < 4; ++kk) {
                const int q0 = (2 * kk)     ^ gid;
                const int q1 = (2 * kk + 1) ^ gid;

                uint32_t a[2][4];
                #pragma unroll
                for (int mt = 0; mt < 2; ++mt) {
                    const int r0 = aRow0 + mt * 16;
                    const int r1 = r0 + 8;
                    a[mt][0] = *(const uint32_t*)(sA + r0 * 128 + co + (q0 << 4));
                    a[mt][1] = *(const uint32_t*)(sA + r1 * 128 + co + (q0 << 4));
                    a[mt][2] = *(const uint32_t*)(sA + r0 * 128 + co + (q1 << 4));
                    a[mt][3] = *(const uint32_t*)(sA + r1 * 128 + co + (q1 << 4));
                }
                uint32_t b[8][2];
                #pragma unroll
                for (int nt = 0; nt < 8; ++nt) {
                    const int rb = bRow0 + nt * 8;
                    b[nt][0] = *(const uint32_t*)(sB + rb * 128 + co + (q0 << 4));
                    b[nt][1] = *(const uint32_t*)(sB + rb * 128 + co + (q1 << 4));
                }
                #pragma unroll
                for (int nt = 0; nt < 8; ++nt)
                    #pragma unroll
                    for (int mt = 0; mt < 2; ++mt)
                        mma_tf32(acc[mt][nt], a[mt], b[nt]);
            }
        }

        if (lid == 0) mbar_arrive(sb + SM_BAR + s * 16 + 8);
        if (++s == STAGES) { s = 0; fp ^= 1; }
    }

    // ---------------- Epilogue: registers -> GMEM (+bias) ----------------
    #pragma unroll
    for (int mt = 0; mt < 2; ++mt) {
        #pragma unroll
        for (int h = 0; h < 2; ++h) {
            const int row = m_base + warpM * 32 + mt * 16 + gid + h * 8;
            float* __restrict__ orow = out + (size_t)row * 4096;
            #pragma unroll
            for (int nt = 0; nt < 8; ++nt) {
                const int col = n_base + warpN * 64 + nt * 8 + tid4 * 2;
                const float2 bv = __ldg((const float2*)(bias + col));
                float2 v;
                v.x = acc[mt][nt][h * 2 + 0] + bv.x;
                v.y = acc[mt][nt][h * 2 + 1] + bv.y;
                *(float2*)(orow + col) = v;
            }
        }
    }
}

// ---------------------------------------------------------------------------
// Host launch (graph-capturable: host-side setup + one kernel launch)
// ---------------------------------------------------------------------------
typedef CUresult (*EncodeTiledFn)(
    CUtensorMap*, CUtensorMapDataType, cuuint32_t, void*,
    const cuuint64_t*, const cuuint64_t*, const cuuint32_t*, const cuuint32_t*,
    CUtensorMapInterleave, CUtensorMapSwizzle, CUtensorMapL2promotion,
    CUtensorMapFloatOOBfill);

extern "C" void kernel_launch(void* const* d_in, const int* in_sizes, int n_in,
                              void* d_out, int out_size) {
    const float* x    = (const float*)d_in[0];   // [4096, 4096]
    const float* w    = (const float*)d_in[1];   // [4096, 4096]
    const float* bias = (const float*)d_in[2];   // [4096]
    float* out        = (float*)d_out;

    void* fn = nullptr;
    cudaDriverEntryPointQueryResult qr;
    cudaGetDriverEntryPoint("cuTensorMapEncodeTiled", &fn, cudaEnableDefault, &qr);
    EncodeTiledFn encode = (EncodeTiledFn)fn;

    alignas(64) CUtensorMap tA, tB;
    cuuint64_t dims[2]    = {4096, 4096};          // {K elems, rows}
    cuuint64_t strides[1] = {4096 * sizeof(float)};
    cuuint32_t box[2]     = {K_SLAB, 128};         // 128B x 128 rows
    cuuint32_t es[2]      = {1, 1};

    encode(&tA, CU_TENSOR_MAP_DATA_TYPE_FLOAT32, 2, (void*)x,
           dims, strides, box, es,
           CU_TENSOR_MAP_INTERLEAVE_NONE, CU_TENSOR_MAP_SWIZZLE_128B,
           CU_TENSOR_MAP_L2_PROMOTION_L2_256B, CU_TENSOR_MAP_FLOAT_OOB_FILL_NONE);
    encode(&tB, CU_TENSOR_MAP_DATA_TYPE_FLOAT32, 2, (void*)w,
           dims, strides, box, es,
           CU_TENSOR_MAP_INTERLEAVE_NONE, CU_TENSOR_MAP_SWIZZLE_128B,
           CU_TENSOR_MAP_L2_PROMOTION_L2_256B, CU_TENSOR_MAP_FLOAT_OOB_FILL_NONE);

    cudaFuncSetAttribute(gemm_tf32_kernel,
                         cudaFuncAttributeMaxDynamicSharedMemorySize, SMEM_TOTAL);

    dim3 grid(4096 / N_TILE, 4096 / M_TILE, 1);   // (32, 32)
    gemm_tf32_kernel<<<grid, 288, SMEM_TOTAL>>>(tA, tB, bias, out);
}